// round 9
// baseline (speedup 1.0000x reference)
#include <cuda_runtime.h>
#include <cuda_bf16.h>

#define NW 8192
#define NS 8192
#define FD 1024
#define EMB 128
#define QN 1024
#define NC 80
#define POSCAP 512

// ---------------- scratch (device globals; no allocation) ----------------
__device__ float g_q[NW * EMB];          // weak encodings
__device__ float g_k[NS * EMB];          // strong encodings
__device__ int   g_rank[NW];
__device__ int   g_idx[NW];
__device__ int   g_valid[NW];
__device__ int   g_posS[NC * POSCAP];
__device__ int   g_histS[NC];
__device__ float g_m[2 * NW];            // per-half running max
__device__ float g_l[2 * NW];            // per-half running sumexp
__device__ float g_psum[32];
__device__ float g_pcnt[32];

// ---------------- helpers ----------------
__device__ __forceinline__ uint2 f4bf(float4 v) {
    __nv_bfloat162 lo = __floats2bfloat162_rn(v.x, v.y);
    __nv_bfloat162 hi = __floats2bfloat162_rn(v.z, v.w);
    uint2 r;
    r.x = *reinterpret_cast<unsigned int*>(&lo);
    r.y = *reinterpret_cast<unsigned int*>(&hi);
    return r;
}

__device__ __forceinline__ void ldsm4(unsigned &r0, unsigned &r1, unsigned &r2, unsigned &r3, unsigned addr) {
    asm volatile("ldmatrix.sync.aligned.m8n8.x4.shared.b16 {%0,%1,%2,%3}, [%4];"
                 : "=r"(r0), "=r"(r1), "=r"(r2), "=r"(r3) : "r"(addr));
}
__device__ __forceinline__ void ldsm4t(unsigned &r0, unsigned &r1, unsigned &r2, unsigned &r3, unsigned addr) {
    asm volatile("ldmatrix.sync.aligned.m8n8.x4.trans.shared.b16 {%0,%1,%2,%3}, [%4];"
                 : "=r"(r0), "=r"(r1), "=r"(r2), "=r"(r3) : "r"(addr));
}
__device__ __forceinline__ void mma16816(float* c, const unsigned* a, unsigned b0, unsigned b1) {
    asm volatile("mma.sync.aligned.m16n8k16.row.col.f32.bf16.bf16.f32 "
                 "{%0,%1,%2,%3}, {%4,%5,%6,%7}, {%8,%9}, {%0,%1,%2,%3};"
                 : "+f"(c[0]), "+f"(c[1]), "+f"(c[2]), "+f"(c[3])
                 : "r"(a[0]), "r"(a[1]), "r"(a[2]), "r"(a[3]), "r"(b0), "r"(b1));
}

// FMA-pipe exp for x <= 0: magic-number range reduction + deg-5 Taylor.
// rel err ~2e-6; keeps exp off the MUFU pipe (logits bottleneck).
__device__ __forceinline__ float fexp(float x) {
    x = fmaxf(x, -80.f);
    float z = fmaf(x, 1.442695041f, 12582912.f);   // + 1.5*2^23 rounds to nearest int
    int   ni = __float_as_int(z) - 0x4B400000;
    float n  = z - 12582912.f;
    float r  = fmaf(n, -0.69314718f, x);           // r in [-0.347, 0.347]
    float p  = 8.3333333e-3f;
    p = fmaf(p, r, 4.1666667e-2f);
    p = fmaf(p, r, 0.16666667f);
    p = fmaf(p, r, 0.5f);
    p = fmaf(p, r, 1.0f);
    p = fmaf(p, r, 1.0f);
    return p * __int_as_float((ni + 127) << 23);
}

// ---------------- label logic ----------------
__global__ void label_scan_kernel(const int* __restrict__ slab,
                                  const int* __restrict__ wlab) {
    const int b = blockIdx.x;
    const bool strong = b < NC;
    const int c = strong ? b : b - NC;
    const int* lab = strong ? slab : wlab;
    __shared__ int wsum[8];
    const int tid = threadIdx.x, lane = tid & 31, wid = tid >> 5;
    int running = 0;
    for (int base = 0; base < NS; base += 256) {
        int j = base + tid;
        int ind = (lab[j] == c) ? 1 : 0;
        int x = ind;
#pragma unroll
        for (int o = 1; o < 32; o <<= 1) {
            int y = __shfl_up_sync(0xffffffffu, x, o);
            if (lane >= o) x += y;
        }
        if (lane == 31) wsum[wid] = x;
        __syncthreads();
        int pre = 0, tot = 0;
#pragma unroll
        for (int ww = 0; ww < 8; ww++) {
            if (ww < wid) pre += wsum[ww];
            tot += wsum[ww];
        }
        int excl = running + pre + x - ind;
        if (ind) {
            if (strong) { if (excl < POSCAP) g_posS[c * POSCAP + excl] = j; }
            else g_rank[j] = excl;
        }
        running += tot;
        __syncthreads();
    }
    if (strong && tid == 0) g_histS[c] = running;
}

__global__ void idx_kernel(const int* __restrict__ wlab) {
    int i = blockIdx.x * 256 + threadIdx.x;
    int c = wlab[i];
    int inrange = (c >= 0 && c < NC) ? 1 : 0;
    int cc = inrange ? c : 0;
    int cnt = g_histS[cc];
    int valid = (inrange && cnt > 0) ? 1 : 0;
    int sel = g_rank[i] % (cnt > 0 ? cnt : 1);
    if (sel >= POSCAP || sel < 0) sel = 0;
    g_idx[i] = valid ? g_posS[cc * POSCAP + sel] : 0;
    g_valid[i] = valid;
}

// ---------------- fused dual encoder GEMM (R4 tiling, single-sync, occ 2) ----
// blocks [0,64): q = feats_weak @ Wq + bq ; blocks [64,128): k = feats_strong @ Wk + bk
// BM=128, BN=128(full), BK=32, 8 warps (4x2), bf16 mma, fp32 acc.
__device__ __forceinline__ void gemm_load(const float* __restrict__ A, const float* __restrict__ B,
                                          int m0, int kt, int tid, float4* ra, float4* rb) {
    const float* Ap = A + m0 * FD + kt * 32;
    const float* Bp = B + kt * 32 * EMB;
#pragma unroll
    for (int it = 0; it < 4; it++) {
        int lin = it * 256 + tid;
        ra[it] = *reinterpret_cast<const float4*>(Ap + (lin >> 3) * FD + (lin & 7) * 4);
        rb[it] = *reinterpret_cast<const float4*>(Bp + (lin >> 5) * EMB + (lin & 31) * 4);
    }
}
__device__ __forceinline__ void gemm_sts(__nv_bfloat16 (*sA)[40], __nv_bfloat16 (*sB)[136],
                                         int tid, const float4* ra, const float4* rb) {
#pragma unroll
    for (int it = 0; it < 4; it++) {
        int lin = it * 256 + tid;
        *reinterpret_cast<uint2*>(&sA[lin >> 3][(lin & 7) * 4]) = f4bf(ra[it]);
        *reinterpret_cast<uint2*>(&sB[lin >> 5][(lin & 31) * 4]) = f4bf(rb[it]);
    }
}

__global__ __launch_bounds__(256, 2) void encoder_gemm_kernel(
    const float* __restrict__ fw, const float* __restrict__ fs,
    const float* __restrict__ Wq, const float* __restrict__ bq,
    const float* __restrict__ Wk, const float* __restrict__ bk) {
    __shared__ __align__(16) __nv_bfloat16 sA[2][128][40];   // pad: 80B row stride
    __shared__ __align__(16) __nv_bfloat16 sB[2][32][136];   // pad: 272B row stride
    const int tid = threadIdx.x, lane = tid & 31, wid = tid >> 5;
    const int wm = wid >> 1, wn = wid & 1;
    const float *A, *B, *bias;
    float* C;
    if (blockIdx.x < 64) { A = fw; B = Wq; bias = bq; C = g_q; }
    else                 { A = fs; B = Wk; bias = bk; C = g_k; }
    const int m0 = (blockIdx.x & 63) * 128;

    float acc[2][8][4];
#pragma unroll
    for (int mt = 0; mt < 2; mt++)
#pragma unroll
        for (int nt = 0; nt < 8; nt++)
#pragma unroll
            for (int j = 0; j < 4; j++) acc[mt][nt][j] = 0.f;

    float4 ra[4], rb[4];
    gemm_load(A, B, m0, 0, tid, ra, rb);
    gemm_sts(sA[0], sB[0], tid, ra, rb);
    __syncthreads();

    for (int kt = 0; kt < FD / 32; kt++) {
        const int buf = kt & 1;
        if (kt < FD / 32 - 1) gemm_load(A, B, m0, kt + 1, tid, ra, rb);
        unsigned abase = (unsigned)__cvta_generic_to_shared(&sA[buf][0][0]);
        unsigned bbase = (unsigned)__cvta_generic_to_shared(&sB[buf][0][0]);
#pragma unroll
        for (int ks = 0; ks < 2; ks++) {
            unsigned af[2][4], bfr[4][4];
#pragma unroll
            for (int mt = 0; mt < 2; mt++) {
                int row = wm * 32 + mt * 16 + (lane & 15);
                int col = ks * 16 + (lane >> 4) * 8;
                ldsm4(af[mt][0], af[mt][1], af[mt][2], af[mt][3],
                      abase + (unsigned)(row * 40 + col) * 2u);
            }
#pragma unroll
            for (int p = 0; p < 4; p++) {
                int qd = lane >> 3;
                int row = ks * 16 + (qd & 1) * 8 + (lane & 7);
                int col = wn * 64 + p * 16 + (qd >> 1) * 8;
                ldsm4t(bfr[p][0], bfr[p][1], bfr[p][2], bfr[p][3],
                       bbase + (unsigned)(row * 136 + col) * 2u);
            }
#pragma unroll
            for (int nt = 0; nt < 8; nt++) {
                unsigned b0 = bfr[nt >> 1][(nt & 1) * 2], b1 = bfr[nt >> 1][(nt & 1) * 2 + 1];
                mma16816(acc[0][nt], af[0], b0, b1);
                mma16816(acc[1][nt], af[1], b0, b1);
            }
        }
        // single-sync double buffer: write next tile to other buffer, then one barrier.
        if (kt < FD / 32 - 1) gemm_sts(sA[buf ^ 1], sB[buf ^ 1], tid, ra, rb);
        __syncthreads();
    }
    const int g = lane >> 2, qd2 = (lane & 3) * 2;
#pragma unroll
    for (int mt = 0; mt < 2; mt++) {
        int r0 = m0 + wm * 32 + mt * 16 + g;
#pragma unroll
        for (int nt = 0; nt < 8; nt++) {
            int c = wn * 64 + nt * 8 + qd2;
            float bx = bias[c], by = bias[c + 1];
            float2 v0 = make_float2(acc[mt][nt][0] + bx, acc[mt][nt][1] + by);
            float2 v1 = make_float2(acc[mt][nt][2] + bx, acc[mt][nt][3] + by);
            *reinterpret_cast<float2*>(&C[r0 * EMB + c]) = v0;
            *reinterpret_cast<float2*>(&C[(r0 + 8) * EMB + c]) = v1;
        }
    }
}

// ---------------- logits GEMM + streaming logsumexp (R4 structure + fexp) ----
// grid 128: (rowblk = bid>>1) * 128 rows, half = bid&1 covering 512 of QN cols.
__global__ __launch_bounds__(256, 1) void logits_kernel(const float* __restrict__ queue) {
    __shared__ __align__(16) __nv_bfloat16 sT[128][136];
    const int tid = threadIdx.x, lane = tid & 31, w = tid >> 5;
    const int m0 = (blockIdx.x >> 1) * 128, n0 = (blockIdx.x & 1) * 512;

    // stage q tile (128x128 fp32 -> bf16): 4096 float4, 16 iters
#pragma unroll
    for (int it = 0; it < 16; it++) {
        int lin = it * 256 + tid;
        float4 v = *reinterpret_cast<const float4*>(g_q + (m0 + (lin >> 5)) * EMB + (lin & 31) * 4);
        *reinterpret_cast<uint2*>(&sT[lin >> 5][(lin & 31) * 4]) = f4bf(v);
    }
    __syncthreads();
    unsigned sbase = (unsigned)__cvta_generic_to_shared(&sT[0][0]);
    unsigned af[8][4];
#pragma unroll
    for (int ks = 0; ks < 8; ks++) {
        int row = w * 16 + (lane & 15);
        int col = ks * 16 + (lane >> 4) * 8;
        ldsm4(af[ks][0], af[ks][1], af[ks][2], af[ks][3],
              sbase + (unsigned)(row * 136 + col) * 2u);
    }
    __syncthreads();

    float m0r = -1e30f, m1r = -1e30f, l0r = 0.f, l1r = 0.f;
    for (int ch = 0; ch < 4; ch++) {
#pragma unroll
        for (int it = 0; it < 16; it++) {
            int lin = it * 256 + tid;
            float4 v = *reinterpret_cast<const float4*>(queue + (lin >> 5) * QN + n0 + ch * 128 + (lin & 31) * 4);
            *reinterpret_cast<uint2*>(&sT[lin >> 5][(lin & 31) * 4]) = f4bf(v);
        }
        __syncthreads();
        float acc[16][4];
#pragma unroll
        for (int nt = 0; nt < 16; nt++) { acc[nt][0] = acc[nt][1] = acc[nt][2] = acc[nt][3] = 0.f; }
#pragma unroll
        for (int ks = 0; ks < 8; ks++) {
            unsigned bfr[8][4];
#pragma unroll
            for (int p = 0; p < 8; p++) {
                int qd = lane >> 3;
                int row = ks * 16 + (qd & 1) * 8 + (lane & 7);
                int col = p * 16 + (qd >> 1) * 8;
                ldsm4t(bfr[p][0], bfr[p][1], bfr[p][2], bfr[p][3],
                       sbase + (unsigned)(row * 136 + col) * 2u);
            }
#pragma unroll
            for (int nt = 0; nt < 16; nt++)
                mma16816(acc[nt], af[ks], bfr[nt >> 1][(nt & 1) * 2], bfr[nt >> 1][(nt & 1) * 2 + 1]);
        }
        // online logsumexp update: thread holds rows g and g+8 (g = lane>>2)
        float c0 = -1e30f, c1 = -1e30f;
#pragma unroll
        for (int nt = 0; nt < 16; nt++) {
            c0 = fmaxf(c0, fmaxf(acc[nt][0], acc[nt][1]));
            c1 = fmaxf(c1, fmaxf(acc[nt][2], acc[nt][3]));
        }
        c0 = fmaxf(c0, __shfl_xor_sync(0xffffffffu, c0, 1));
        c0 = fmaxf(c0, __shfl_xor_sync(0xffffffffu, c0, 2));
        c1 = fmaxf(c1, __shfl_xor_sync(0xffffffffu, c1, 1));
        c1 = fmaxf(c1, __shfl_xor_sync(0xffffffffu, c1, 2));
        float n0m = fmaxf(m0r, c0), n1m = fmaxf(m1r, c1);
        float s0 = 0.f, s1 = 0.f;
#pragma unroll
        for (int nt = 0; nt < 16; nt++) {
            s0 += fexp(acc[nt][0] - n0m) + fexp(acc[nt][1] - n0m);
            s1 += fexp(acc[nt][2] - n1m) + fexp(acc[nt][3] - n1m);
        }
        s0 += __shfl_xor_sync(0xffffffffu, s0, 1);
        s0 += __shfl_xor_sync(0xffffffffu, s0, 2);
        s1 += __shfl_xor_sync(0xffffffffu, s1, 1);
        s1 += __shfl_xor_sync(0xffffffffu, s1, 2);
        l0r = l0r * fexp(m0r - n0m) + s0; m0r = n0m;
        l1r = l1r * fexp(m1r - n1m) + s1; m1r = n1m;
        __syncthreads();
    }
    if ((lane & 3) == 0) {
        int half = blockIdx.x & 1;
        int r = m0 + w * 16 + (lane >> 2);
        g_m[half * NW + r] = m0r;      g_l[half * NW + r] = l0r;
        g_m[half * NW + r + 8] = m1r;  g_l[half * NW + r + 8] = l1r;
    }
}

// ---------------- per-row CE + partial reduction ----------------
__global__ void row_ce_kernel() {
    const int tid = threadIdx.x, lane = tid & 31, wid = tid >> 5;
    int i = blockIdx.x * 256 + tid;
    float ma = g_m[i], la = g_l[i], mb = g_m[NW + i], lb = g_l[NW + i];
    float M = fmaxf(ma, mb);
    float L = la * fexp(ma - M) + lb * fexp(mb - M);
    const float4* qa = reinterpret_cast<const float4*>(g_q + i * EMB);
    const float4* ka = reinterpret_cast<const float4*>(g_k + g_idx[i] * EMB);
    float s = 0.f;
#pragma unroll
    for (int j = 0; j < EMB / 4; j++) {
        float4 a = qa[j], b = ka[j];
        s += a.x * b.x + a.y * b.y + a.z * b.z + a.w * b.w;
    }
    float lpos = s;
    float Mf = fmaxf(M, lpos);
    float Lf = L * fexp(M - Mf) + fexp(lpos - Mf);
    float ce = Mf + logf(Lf) - lpos;
    float v = g_valid[i] ? 1.f : 0.f;
    float aS = ce * v, cS = v;
#pragma unroll
    for (int o = 16; o; o >>= 1) {
        aS += __shfl_xor_sync(0xffffffffu, aS, o);
        cS += __shfl_xor_sync(0xffffffffu, cS, o);
    }
    __shared__ float rs[8], rc[8];
    if (lane == 0) { rs[wid] = aS; rc[wid] = cS; }
    __syncthreads();
    if (tid == 0) {
        float A = 0, C = 0;
#pragma unroll
        for (int ww = 0; ww < 8; ww++) { A += rs[ww]; C += rc[ww]; }
        g_psum[blockIdx.x] = A;
        g_pcnt[blockIdx.x] = C;
    }
}

__global__ void final_kernel(float* out) {
    int lane = threadIdx.x;
    float s = g_psum[lane], c = g_pcnt[lane];
#pragma unroll
    for (int o = 16; o; o >>= 1) {
        s += __shfl_xor_sync(0xffffffffu, s, o);
        c += __shfl_xor_sync(0xffffffffu, c, o);
    }
    if (lane == 0) out[0] = s / fmaxf(c, 1.f);
}

// ---------------- launch ----------------
extern "C" void kernel_launch(void* const* d_in, const int* in_sizes, int n_in,
                              void* d_out, int out_size) {
    const float* fs    = (const float*)d_in[0];   // feats_strong [8192,1024]
    const float* fw    = (const float*)d_in[1];   // feats_weak   [8192,1024]
    const int*   slab  = (const int*)d_in[2];     // strong_labels (int32)
    const int*   wlab  = (const int*)d_in[3];     // weak_labels   (int32)
    const float* Wq    = (const float*)d_in[4];
    const float* bq    = (const float*)d_in[5];
    const float* Wk    = (const float*)d_in[6];
    const float* bk    = (const float*)d_in[7];
    const float* queue = (const float*)d_in[8];   // [1024,128] flat
    float* out = (float*)d_out;

    label_scan_kernel<<<2 * NC, 256>>>(slab, wlab);
    idx_kernel<<<NW / 256, 256>>>(wlab);
    encoder_gemm_kernel<<<128, 256>>>(fw, fs, Wq, bq, Wk, bk);
    logits_kernel<<<128, 256>>>(queue);
    row_ce_kernel<<<NW / 256, 256>>>();
    final_kernel<<<1, 32>>>(out);
}

// round 10
// speedup vs baseline: 1.1494x; 1.1494x over previous
#include <cuda_runtime.h>
#include <cuda_bf16.h>

#define NW 8192
#define NS 8192
#define FD 1024
#define EMB 128
#define QN 1024
#define NC 80
#define POSCAP 512

// ---------------- scratch (device globals; no allocation) ----------------
__device__ float g_q[NW * EMB];          // weak encodings
__device__ float g_k[NS * EMB];          // strong encodings
__device__ int   g_rank[NW];
__device__ int   g_idx[NW];
__device__ int   g_valid[NW];
__device__ int   g_posS[NC * POSCAP];
__device__ int   g_histS[NC];
__device__ float g_m[2 * NW];            // per-half running max
__device__ float g_l[2 * NW];            // per-half running sumexp
__device__ float g_psum[32];
__device__ float g_pcnt[32];

// ---------------- helpers ----------------
__device__ __forceinline__ uint2 f4bf(float4 v) {
    __nv_bfloat162 lo = __floats2bfloat162_rn(v.x, v.y);
    __nv_bfloat162 hi = __floats2bfloat162_rn(v.z, v.w);
    uint2 r;
    r.x = *reinterpret_cast<unsigned int*>(&lo);
    r.y = *reinterpret_cast<unsigned int*>(&hi);
    return r;
}

__device__ __forceinline__ void ldsm4(unsigned &r0, unsigned &r1, unsigned &r2, unsigned &r3, unsigned addr) {
    asm volatile("ldmatrix.sync.aligned.m8n8.x4.shared.b16 {%0,%1,%2,%3}, [%4];"
                 : "=r"(r0), "=r"(r1), "=r"(r2), "=r"(r3) : "r"(addr));
}
__device__ __forceinline__ void ldsm4t(unsigned &r0, unsigned &r1, unsigned &r2, unsigned &r3, unsigned addr) {
    asm volatile("ldmatrix.sync.aligned.m8n8.x4.trans.shared.b16 {%0,%1,%2,%3}, [%4];"
                 : "=r"(r0), "=r"(r1), "=r"(r2), "=r"(r3) : "r"(addr));
}
__device__ __forceinline__ void mma16816(float* c, const unsigned* a, unsigned b0, unsigned b1) {
    asm volatile("mma.sync.aligned.m16n8k16.row.col.f32.bf16.bf16.f32 "
                 "{%0,%1,%2,%3}, {%4,%5,%6,%7}, {%8,%9}, {%0,%1,%2,%3};"
                 : "+f"(c[0]), "+f"(c[1]), "+f"(c[2]), "+f"(c[3])
                 : "r"(a[0]), "r"(a[1]), "r"(a[2]), "r"(a[3]), "r"(b0), "r"(b1));
}

// ---------------- label logic ----------------
__global__ void label_scan_kernel(const int* __restrict__ slab,
                                  const int* __restrict__ wlab) {
    const int b = blockIdx.x;
    const bool strong = b < NC;
    const int c = strong ? b : b - NC;
    const int* lab = strong ? slab : wlab;
    __shared__ int wsum[8];
    const int tid = threadIdx.x, lane = tid & 31, wid = tid >> 5;
    int running = 0;
    for (int base = 0; base < NS; base += 256) {
        int j = base + tid;
        int ind = (lab[j] == c) ? 1 : 0;
        int x = ind;
#pragma unroll
        for (int o = 1; o < 32; o <<= 1) {
            int y = __shfl_up_sync(0xffffffffu, x, o);
            if (lane >= o) x += y;
        }
        if (lane == 31) wsum[wid] = x;
        __syncthreads();
        int pre = 0, tot = 0;
#pragma unroll
        for (int ww = 0; ww < 8; ww++) {
            if (ww < wid) pre += wsum[ww];
            tot += wsum[ww];
        }
        int excl = running + pre + x - ind;
        if (ind) {
            if (strong) { if (excl < POSCAP) g_posS[c * POSCAP + excl] = j; }
            else g_rank[j] = excl;
        }
        running += tot;
        __syncthreads();
    }
    if (strong && tid == 0) g_histS[c] = running;
}

__global__ void idx_kernel(const int* __restrict__ wlab) {
    int i = blockIdx.x * 256 + threadIdx.x;
    int c = wlab[i];
    int inrange = (c >= 0 && c < NC) ? 1 : 0;
    int cc = inrange ? c : 0;
    int cnt = g_histS[cc];
    int valid = (inrange && cnt > 0) ? 1 : 0;
    int sel = g_rank[i] % (cnt > 0 ? cnt : 1);
    if (sel >= POSCAP || sel < 0) sel = 0;
    g_idx[i] = valid ? g_posS[cc * POSCAP + sel] : 0;
    g_valid[i] = valid;
}

// ---------------- fused dual encoder GEMM (512 threads, 16 warps 4x4) ------
// blocks [0,64): q = feats_weak @ Wq + bq ; blocks [64,128): k = feats_strong @ Wk + bk
// BM=128, BN=128(full), BK=32. Single-sync double buffer. bf16 mma, fp32 acc.
__device__ __forceinline__ void enc_load(const float* __restrict__ A, const float* __restrict__ B,
                                         int m0, int kt, int tid, float4* ra, float4* rb) {
    const float* Ap = A + m0 * FD + kt * 32;
    const float* Bp = B + kt * 32 * EMB;
#pragma unroll
    for (int it = 0; it < 2; it++) {
        int lin = it * 512 + tid;
        ra[it] = *reinterpret_cast<const float4*>(Ap + (lin >> 3) * FD + (lin & 7) * 4);
        rb[it] = *reinterpret_cast<const float4*>(Bp + (lin >> 5) * EMB + (lin & 31) * 4);
    }
}
__device__ __forceinline__ void enc_sts(__nv_bfloat16 (*sA)[40], __nv_bfloat16 (*sB)[136],
                                        int tid, const float4* ra, const float4* rb) {
#pragma unroll
    for (int it = 0; it < 2; it++) {
        int lin = it * 512 + tid;
        *reinterpret_cast<uint2*>(&sA[lin >> 3][(lin & 7) * 4]) = f4bf(ra[it]);
        *reinterpret_cast<uint2*>(&sB[lin >> 5][(lin & 31) * 4]) = f4bf(rb[it]);
    }
}

__global__ __launch_bounds__(512, 1) void encoder_gemm_kernel(
    const float* __restrict__ fw, const float* __restrict__ fs,
    const float* __restrict__ Wq, const float* __restrict__ bq,
    const float* __restrict__ Wk, const float* __restrict__ bk) {
    __shared__ __align__(16) __nv_bfloat16 sA[2][128][40];   // 80B row stride
    __shared__ __align__(16) __nv_bfloat16 sB[2][32][136];   // 272B row stride
    const int tid = threadIdx.x, lane = tid & 31, wid = tid >> 5;
    const int wm = wid >> 2, wn = wid & 3;   // 4 x 4 warps over 128 x 128
    const float *A, *B, *bias;
    float* C;
    if (blockIdx.x < 64) { A = fw; B = Wq; bias = bq; C = g_q; }
    else                 { A = fs; B = Wk; bias = bk; C = g_k; }
    const int m0 = (blockIdx.x & 63) * 128;

    float acc[2][4][4];
#pragma unroll
    for (int mt = 0; mt < 2; mt++)
#pragma unroll
        for (int nt = 0; nt < 4; nt++)
#pragma unroll
            for (int j = 0; j < 4; j++) acc[mt][nt][j] = 0.f;

    float4 ra[2], rb[2];
    enc_load(A, B, m0, 0, tid, ra, rb);
    enc_sts(sA[0], sB[0], tid, ra, rb);
    __syncthreads();

    for (int kt = 0; kt < FD / 32; kt++) {
        const int buf = kt & 1;
        if (kt < FD / 32 - 1) enc_load(A, B, m0, kt + 1, tid, ra, rb);
        unsigned abase = (unsigned)__cvta_generic_to_shared(&sA[buf][0][0]);
        unsigned bbase = (unsigned)__cvta_generic_to_shared(&sB[buf][0][0]);
#pragma unroll
        for (int ks = 0; ks < 2; ks++) {
            unsigned af[2][4], bfr[2][4];
#pragma unroll
            for (int mt = 0; mt < 2; mt++) {
                int row = wm * 32 + mt * 16 + (lane & 15);
                int col = ks * 16 + (lane >> 4) * 8;
                ldsm4(af[mt][0], af[mt][1], af[mt][2], af[mt][3],
                      abase + (unsigned)(row * 40 + col) * 2u);
            }
#pragma unroll
            for (int p = 0; p < 2; p++) {
                int qd = lane >> 3;
                int row = ks * 16 + (qd & 1) * 8 + (lane & 7);
                int col = wn * 32 + p * 16 + (qd >> 1) * 8;
                ldsm4t(bfr[p][0], bfr[p][1], bfr[p][2], bfr[p][3],
                       bbase + (unsigned)(row * 136 + col) * 2u);
            }
#pragma unroll
            for (int nt = 0; nt < 4; nt++) {
                unsigned b0 = bfr[nt >> 1][(nt & 1) * 2], b1 = bfr[nt >> 1][(nt & 1) * 2 + 1];
                mma16816(acc[0][nt], af[0], b0, b1);
                mma16816(acc[1][nt], af[1], b0, b1);
            }
        }
        // single-sync double buffer: write next tile to other buffer, then one barrier.
        if (kt < FD / 32 - 1) enc_sts(sA[buf ^ 1], sB[buf ^ 1], tid, ra, rb);
        __syncthreads();
    }
    const int g = lane >> 2, qd2 = (lane & 3) * 2;
#pragma unroll
    for (int mt = 0; mt < 2; mt++) {
        int r0 = m0 + wm * 32 + mt * 16 + g;
#pragma unroll
        for (int nt = 0; nt < 4; nt++) {
            int c = wn * 32 + nt * 8 + qd2;
            float bx = bias[c], by = bias[c + 1];
            float2 v0 = make_float2(acc[mt][nt][0] + bx, acc[mt][nt][1] + by);
            float2 v1 = make_float2(acc[mt][nt][2] + bx, acc[mt][nt][3] + by);
            *reinterpret_cast<float2*>(&C[r0 * EMB + c]) = v0;
            *reinterpret_cast<float2*>(&C[(r0 + 8) * EMB + c]) = v1;
        }
    }
}

// ---------------- logits GEMM + streaming logsumexp (double-buffered) ------
// grid 128: rowblk = bid>>1 (128 rows), half = bid&1 (512 cols -> 8 chunks of 64).
// Every warp covers ALL chunk columns (per-row lse state stays within one warp).
__global__ __launch_bounds__(256, 1) void logits_kernel(const float* __restrict__ queue) {
    __shared__ __align__(16) __nv_bfloat16 sB[2][128][72];   // 144B row stride
    const int tid = threadIdx.x, lane = tid & 31, w = tid >> 5;
    const int m0 = (blockIdx.x >> 1) * 128, n0 = (blockIdx.x & 1) * 512;
    unsigned base0 = (unsigned)__cvta_generic_to_shared(&sB[0][0][0]);
    unsigned base1 = (unsigned)__cvta_generic_to_shared(&sB[1][0][0]);

    // extract A fragments in two passes through sB[0] (k-cols 0:64 then 64:128)
    unsigned af[8][4];
#pragma unroll
    for (int s = 0; s < 2; s++) {
        if (s == 1) __syncthreads();   // prior ldsm reads of sB[0] before overwrite
#pragma unroll
        for (int it = 0; it < 8; it++) {
            int lin = it * 256 + tid;
            int row = lin >> 4, c4 = (lin & 15) * 4;
            float4 v = *reinterpret_cast<const float4*>(g_q + (m0 + row) * EMB + s * 64 + c4);
            *reinterpret_cast<uint2*>(&sB[0][row][c4]) = f4bf(v);
        }
        __syncthreads();
#pragma unroll
        for (int k = 0; k < 4; k++) {
            int row = w * 16 + (lane & 15);
            int col = k * 16 + (lane >> 4) * 8;
            ldsm4(af[s * 4 + k][0], af[s * 4 + k][1], af[s * 4 + k][2], af[s * 4 + k][3],
                  base0 + (unsigned)(row * 72 + col) * 2u);
        }
    }

    // preload chunk 0 into sB[1]
    float4 rq[8];
#pragma unroll
    for (int it = 0; it < 8; it++) {
        int lin = it * 256 + tid;
        rq[it] = *reinterpret_cast<const float4*>(queue + (lin >> 4) * QN + n0 + (lin & 15) * 4);
    }
#pragma unroll
    for (int it = 0; it < 8; it++) {
        int lin = it * 256 + tid;
        *reinterpret_cast<uint2*>(&sB[1][lin >> 4][(lin & 15) * 4]) = f4bf(rq[it]);
    }
    __syncthreads();   // also orders af reads of sB[0] before chunk1 overwrites it

    float m0r = -1e30f, m1r = -1e30f, l0r = 0.f, l1r = 0.f;
    for (int ch = 0; ch < 8; ch++) {
        const int rb = (ch & 1) ^ 1;           // ch0->buf1, ch1->buf0, ...
        if (ch < 7) {
#pragma unroll
            for (int it = 0; it < 8; it++) {
                int lin = it * 256 + tid;
                rq[it] = *reinterpret_cast<const float4*>(
                    queue + (lin >> 4) * QN + n0 + (ch + 1) * 64 + (lin & 15) * 4);
            }
        }
        unsigned bbase = rb ? base1 : base0;
        float acc[8][4];
#pragma unroll
        for (int nt = 0; nt < 8; nt++) { acc[nt][0] = acc[nt][1] = acc[nt][2] = acc[nt][3] = 0.f; }
#pragma unroll
        for (int ks = 0; ks < 8; ks++) {
            unsigned bfr[4][4];
#pragma unroll
            for (int p = 0; p < 4; p++) {
                int qd = lane >> 3;
                int row = ks * 16 + (qd & 1) * 8 + (lane & 7);
                int col = p * 16 + (qd >> 1) * 8;
                ldsm4t(bfr[p][0], bfr[p][1], bfr[p][2], bfr[p][3],
                       bbase + (unsigned)(row * 72 + col) * 2u);
            }
#pragma unroll
            for (int nt = 0; nt < 8; nt++)
                mma16816(acc[nt], af[ks], bfr[nt >> 1][(nt & 1) * 2], bfr[nt >> 1][(nt & 1) * 2 + 1]);
        }
        // online logsumexp update: thread holds rows g=lane>>2 and g+8 of its warp band
        float c0 = -1e30f, c1 = -1e30f;
#pragma unroll
        for (int nt = 0; nt < 8; nt++) {
            c0 = fmaxf(c0, fmaxf(acc[nt][0], acc[nt][1]));
            c1 = fmaxf(c1, fmaxf(acc[nt][2], acc[nt][3]));
        }
        c0 = fmaxf(c0, __shfl_xor_sync(0xffffffffu, c0, 1));
        c0 = fmaxf(c0, __shfl_xor_sync(0xffffffffu, c0, 2));
        c1 = fmaxf(c1, __shfl_xor_sync(0xffffffffu, c1, 1));
        c1 = fmaxf(c1, __shfl_xor_sync(0xffffffffu, c1, 2));
        float n0m = fmaxf(m0r, c0), n1m = fmaxf(m1r, c1);
        float s0 = 0.f, s1 = 0.f;
#pragma unroll
        for (int nt = 0; nt < 8; nt++) {
            s0 += __expf(acc[nt][0] - n0m) + __expf(acc[nt][1] - n0m);
            s1 += __expf(acc[nt][2] - n1m) + __expf(acc[nt][3] - n1m);
        }
        s0 += __shfl_xor_sync(0xffffffffu, s0, 1);
        s0 += __shfl_xor_sync(0xffffffffu, s0, 2);
        s1 += __shfl_xor_sync(0xffffffffu, s1, 1);
        s1 += __shfl_xor_sync(0xffffffffu, s1, 2);
        l0r = l0r * __expf(m0r - n0m) + s0; m0r = n0m;
        l1r = l1r * __expf(m1r - n1m) + s1; m1r = n1m;
        // store next chunk into the buffer we just finished reading... no: into other buffer
        if (ch < 7) {
#pragma unroll
            for (int it = 0; it < 8; it++) {
                int lin = it * 256 + tid;
                *reinterpret_cast<uint2*>(&sB[rb ^ 1][lin >> 4][(lin & 15) * 4]) = f4bf(rq[it]);
            }
        }
        __syncthreads();
    }
    if ((lane & 3) == 0) {
        int half = blockIdx.x & 1;
        int r = m0 + w * 16 + (lane >> 2);
        g_m[half * NW + r] = m0r;      g_l[half * NW + r] = l0r;
        g_m[half * NW + r + 8] = m1r;  g_l[half * NW + r + 8] = l1r;
    }
}

// ---------------- per-row CE + partial reduction ----------------
__global__ void row_ce_kernel() {
    const int tid = threadIdx.x, lane = tid & 31, wid = tid >> 5;
    int i = blockIdx.x * 256 + tid;
    float ma = g_m[i], la = g_l[i], mb = g_m[NW + i], lb = g_l[NW + i];
    float M = fmaxf(ma, mb);
    float L = la * __expf(ma - M) + lb * __expf(mb - M);
    const float4* qa = reinterpret_cast<const float4*>(g_q + i * EMB);
    const float4* ka = reinterpret_cast<const float4*>(g_k + g_idx[i] * EMB);
    float s = 0.f;
#pragma unroll
    for (int j = 0; j < EMB / 4; j++) {
        float4 a = qa[j], b = ka[j];
        s += a.x * b.x + a.y * b.y + a.z * b.z + a.w * b.w;
    }
    float lpos = s;
    float Mf = fmaxf(M, lpos);
    float Lf = L * __expf(M - Mf) + __expf(lpos - Mf);
    float ce = Mf + logf(Lf) - lpos;
    float v = g_valid[i] ? 1.f : 0.f;
    float aS = ce * v, cS = v;
#pragma unroll
    for (int o = 16; o; o >>= 1) {
        aS += __shfl_xor_sync(0xffffffffu, aS, o);
        cS += __shfl_xor_sync(0xffffffffu, cS, o);
    }
    __shared__ float rs[8], rc[8];
    if (lane == 0) { rs[wid] = aS; rc[wid] = cS; }
    __syncthreads();
    if (tid == 0) {
        float A = 0, C = 0;
#pragma unroll
        for (int ww = 0; ww < 8; ww++) { A += rs[ww]; C += rc[ww]; }
        g_psum[blockIdx.x] = A;
        g_pcnt[blockIdx.x] = C;
    }
}

__global__ void final_kernel(float* out) {
    int lane = threadIdx.x;
    float s = g_psum[lane], c = g_pcnt[lane];
#pragma unroll
    for (int o = 16; o; o >>= 1) {
        s += __shfl_xor_sync(0xffffffffu, s, o);
        c += __shfl_xor_sync(0xffffffffu, c, o);
    }
    if (lane == 0) out[0] = s / fmaxf(c, 1.f);
}

// ---------------- launch ----------------
extern "C" void kernel_launch(void* const* d_in, const int* in_sizes, int n_in,
                              void* d_out, int out_size) {
    const float* fs    = (const float*)d_in[0];   // feats_strong [8192,1024]
    const float* fw    = (const float*)d_in[1];   // feats_weak   [8192,1024]
    const int*   slab  = (const int*)d_in[2];     // strong_labels (int32)
    const int*   wlab  = (const int*)d_in[3];     // weak_labels   (int32)
    const float* Wq    = (const float*)d_in[4];
    const float* bq    = (const float*)d_in[5];
    const float* Wk    = (const float*)d_in[6];
    const float* bk    = (const float*)d_in[7];
    const float* queue = (const float*)d_in[8];   // [1024,128] flat
    float* out = (float*)d_out;

    label_scan_kernel<<<2 * NC, 256>>>(slab, wlab);
    idx_kernel<<<NW / 256, 256>>>(wlab);
    encoder_gemm_kernel<<<128, 512>>>(fw, fs, Wq, bq, Wk, bk);
    logits_kernel<<<128, 256>>>(queue);
    row_ce_kernel<<<NW / 256, 256>>>();
    final_kernel<<<1, 32>>>(out);
}

// round 11
// speedup vs baseline: 1.3053x; 1.1356x over previous
#include <cuda_runtime.h>
#include <cuda_bf16.h>

#define NW 8192
#define NS 8192
#define FD 1024
#define EMB 128
#define QN 1024
#define NC 80
#define POSCAP 512

// ---------------- scratch (device globals; no allocation) ----------------
__device__ float g_q[NW * EMB];          // weak encodings
__device__ float g_k[NS * EMB];          // strong encodings
__device__ int   g_rank[NW];
__device__ int   g_idx[NW];
__device__ int   g_valid[NW];
__device__ int   g_posS[NC * POSCAP];
__device__ int   g_histS[NC];
__device__ float g_m[2 * NW];            // per-half running max
__device__ float g_l[2 * NW];            // per-half running sumexp
__device__ float g_psum[32];
__device__ float g_pcnt[32];

// ---------------- helpers ----------------
__device__ __forceinline__ uint2 f4bf(float4 v) {
    __nv_bfloat162 lo = __floats2bfloat162_rn(v.x, v.y);
    __nv_bfloat162 hi = __floats2bfloat162_rn(v.z, v.w);
    uint2 r;
    r.x = *reinterpret_cast<unsigned int*>(&lo);
    r.y = *reinterpret_cast<unsigned int*>(&hi);
    return r;
}

__device__ __forceinline__ void ldsm4(unsigned &r0, unsigned &r1, unsigned &r2, unsigned &r3, unsigned addr) {
    asm volatile("ldmatrix.sync.aligned.m8n8.x4.shared.b16 {%0,%1,%2,%3}, [%4];"
                 : "=r"(r0), "=r"(r1), "=r"(r2), "=r"(r3) : "r"(addr));
}
__device__ __forceinline__ void ldsm4t(unsigned &r0, unsigned &r1, unsigned &r2, unsigned &r3, unsigned addr) {
    asm volatile("ldmatrix.sync.aligned.m8n8.x4.trans.shared.b16 {%0,%1,%2,%3}, [%4];"
                 : "=r"(r0), "=r"(r1), "=r"(r2), "=r"(r3) : "r"(addr));
}
__device__ __forceinline__ void mma16816(float* c, const unsigned* a, unsigned b0, unsigned b1) {
    asm volatile("mma.sync.aligned.m16n8k16.row.col.f32.bf16.bf16.f32 "
                 "{%0,%1,%2,%3}, {%4,%5,%6,%7}, {%8,%9}, {%0,%1,%2,%3};"
                 : "+f"(c[0]), "+f"(c[1]), "+f"(c[2]), "+f"(c[3])
                 : "r"(a[0]), "r"(a[1]), "r"(a[2]), "r"(a[3]), "r"(b0), "r"(b1));
}

// ---------------- label logic (v3: smem-staged, one global burst) ----------
// blocks [0,80): strong labels -> posS/histS ; blocks [80,160): weak -> rank.
__global__ void label_scan_kernel(const int* __restrict__ slab,
                                  const int* __restrict__ wlab) {
    const int b = blockIdx.x;
    const bool strong = b < NC;
    const int c = strong ? b : b - NC;
    const int* lab = strong ? slab : wlab;
    __shared__ int sl[NS];          // 32 KB
    __shared__ int wsum[8];
    const int tid = threadIdx.x, lane = tid & 31, wid = tid >> 5;

    // one coalesced burst: 8 int4 per thread, all independent (max MLP)
#pragma unroll
    for (int it = 0; it < 8; it++) {
        int lin = it * 256 + tid;
        int4 v = reinterpret_cast<const int4*>(lab)[lin];
        *reinterpret_cast<int4*>(&sl[lin * 4]) = v;
    }
    __syncthreads();

    // phase 1: count matches in this thread's 32-element segment
    const int base = tid * 32;
    int cnt = 0;
#pragma unroll
    for (int j = 0; j < 32; j++) cnt += (sl[base + j] == c) ? 1 : 0;

    // block-wide exclusive scan of cnt
    int x = cnt;
#pragma unroll
    for (int o = 1; o < 32; o <<= 1) {
        int y = __shfl_up_sync(0xffffffffu, x, o);
        if (lane >= o) x += y;
    }
    if (lane == 31) wsum[wid] = x;
    __syncthreads();
    int wpre = 0, tot = 0;
#pragma unroll
    for (int ww = 0; ww < 8; ww++) {
        if (ww < wid) wpre += wsum[ww];
        tot += wsum[ww];
    }
    int pos = wpre + x - cnt;   // exclusive prefix for this segment

    // phase 2: assign occurrence ranks / positions
#pragma unroll
    for (int j = 0; j < 32; j++) {
        int jj = base + j;
        if (sl[jj] == c) {
            if (strong) { if (pos < POSCAP) g_posS[c * POSCAP + pos] = jj; }
            else g_rank[jj] = pos;
            pos++;
        }
    }
    if (strong && tid == 0) g_histS[c] = tot;
}

__global__ void idx_kernel(const int* __restrict__ wlab) {
    int i = blockIdx.x * 256 + threadIdx.x;
    int c = wlab[i];
    int inrange = (c >= 0 && c < NC) ? 1 : 0;
    int cc = inrange ? c : 0;
    int cnt = g_histS[cc];
    int valid = (inrange && cnt > 0) ? 1 : 0;
    int sel = g_rank[i] % (cnt > 0 ? cnt : 1);
    if (sel >= POSCAP || sel < 0) sel = 0;
    g_idx[i] = valid ? g_posS[cc * POSCAP + sel] : 0;
    g_valid[i] = valid;
}

// ---------------- fused dual encoder GEMM (BM=64, 2 CTAs/SM) ---------------
// blocks [0,128): q = feats_weak @ Wq + bq ; [128,256): k = feats_strong @ Wk + bk
// BM=64, BN=128 (full EMB), BK=32, 8 warps (2x4). Single-sync double buffer.
__device__ __forceinline__ void enc_load(const float* __restrict__ A, const float* __restrict__ B,
                                         int m0, int kt, int tid, float4* ra, float4* rb) {
    const float* Ap = A + m0 * FD + kt * 32;
    const float* Bp = B + kt * 32 * EMB;
#pragma unroll
    for (int it = 0; it < 2; it++) {
        int lin = it * 256 + tid;
        ra[it] = *reinterpret_cast<const float4*>(Ap + (lin >> 3) * FD + (lin & 7) * 4);
    }
#pragma unroll
    for (int it = 0; it < 4; it++) {
        int lin = it * 256 + tid;
        rb[it] = *reinterpret_cast<const float4*>(Bp + (lin >> 5) * EMB + (lin & 31) * 4);
    }
}
__device__ __forceinline__ void enc_sts(__nv_bfloat16 (*sA)[40], __nv_bfloat16 (*sB)[136],
                                        int tid, const float4* ra, const float4* rb) {
#pragma unroll
    for (int it = 0; it < 2; it++) {
        int lin = it * 256 + tid;
        *reinterpret_cast<uint2*>(&sA[lin >> 3][(lin & 7) * 4]) = f4bf(ra[it]);
    }
#pragma unroll
    for (int it = 0; it < 4; it++) {
        int lin = it * 256 + tid;
        *reinterpret_cast<uint2*>(&sB[lin >> 5][(lin & 31) * 4]) = f4bf(rb[it]);
    }
}

__global__ __launch_bounds__(256, 2) void encoder_gemm_kernel(
    const float* __restrict__ fw, const float* __restrict__ fs,
    const float* __restrict__ Wq, const float* __restrict__ bq,
    const float* __restrict__ Wk, const float* __restrict__ bk) {
    __shared__ __align__(16) __nv_bfloat16 sA[2][64][40];    // 80B row stride
    __shared__ __align__(16) __nv_bfloat16 sB[2][32][136];   // 272B row stride
    const int tid = threadIdx.x, lane = tid & 31, wid = tid >> 5;
    const int wm = wid >> 2, wn = wid & 3;   // 2 x 4 warps over 64 x 128
    const float *A, *B, *bias;
    float* C;
    if (blockIdx.x < 128) { A = fw; B = Wq; bias = bq; C = g_q; }
    else                  { A = fs; B = Wk; bias = bk; C = g_k; }
    const int m0 = (blockIdx.x & 127) * 64;

    float acc[2][4][4];
#pragma unroll
    for (int mt = 0; mt < 2; mt++)
#pragma unroll
        for (int nt = 0; nt < 4; nt++)
#pragma unroll
            for (int j = 0; j < 4; j++) acc[mt][nt][j] = 0.f;

    float4 ra[2], rb[4];
    enc_load(A, B, m0, 0, tid, ra, rb);
    enc_sts(sA[0], sB[0], tid, ra, rb);
    __syncthreads();

    for (int kt = 0; kt < FD / 32; kt++) {
        const int buf = kt & 1;
        if (kt < FD / 32 - 1) enc_load(A, B, m0, kt + 1, tid, ra, rb);
        unsigned abase = (unsigned)__cvta_generic_to_shared(&sA[buf][0][0]);
        unsigned bbase = (unsigned)__cvta_generic_to_shared(&sB[buf][0][0]);
#pragma unroll
        for (int ks = 0; ks < 2; ks++) {
            unsigned af[2][4], bfr[2][4];
#pragma unroll
            for (int mt = 0; mt < 2; mt++) {
                int row = wm * 32 + mt * 16 + (lane & 15);
                int col = ks * 16 + (lane >> 4) * 8;
                ldsm4(af[mt][0], af[mt][1], af[mt][2], af[mt][3],
                      abase + (unsigned)(row * 40 + col) * 2u);
            }
#pragma unroll
            for (int p = 0; p < 2; p++) {
                int qd = lane >> 3;
                int row = ks * 16 + (qd & 1) * 8 + (lane & 7);
                int col = wn * 32 + p * 16 + (qd >> 1) * 8;
                ldsm4t(bfr[p][0], bfr[p][1], bfr[p][2], bfr[p][3],
                       bbase + (unsigned)(row * 136 + col) * 2u);
            }
#pragma unroll
            for (int nt = 0; nt < 4; nt++) {
                unsigned b0 = bfr[nt >> 1][(nt & 1) * 2], b1 = bfr[nt >> 1][(nt & 1) * 2 + 1];
                mma16816(acc[0][nt], af[0], b0, b1);
                mma16816(acc[1][nt], af[1], b0, b1);
            }
        }
        // single-sync double buffer: write next tile to other buffer, then one barrier.
        if (kt < FD / 32 - 1) enc_sts(sA[buf ^ 1], sB[buf ^ 1], tid, ra, rb);
        __syncthreads();
    }
    const int g = lane >> 2, qd2 = (lane & 3) * 2;
#pragma unroll
    for (int mt = 0; mt < 2; mt++) {
        int r0 = m0 + wm * 32 + mt * 16 + g;
#pragma unroll
        for (int nt = 0; nt < 4; nt++) {
            int c = wn * 32 + nt * 8 + qd2;
            float bx = bias[c], by = bias[c + 1];
            float2 v0 = make_float2(acc[mt][nt][0] + bx, acc[mt][nt][1] + by);
            float2 v1 = make_float2(acc[mt][nt][2] + bx, acc[mt][nt][3] + by);
            *reinterpret_cast<float2*>(&C[r0 * EMB + c]) = v0;
            *reinterpret_cast<float2*>(&C[(r0 + 8) * EMB + c]) = v1;
        }
    }
}

// ---------------- logits GEMM + streaming logsumexp (R10, unchanged) -------
// grid 128: rowblk = bid>>1 (128 rows), half = bid&1 (512 cols -> 8 chunks of 64).
// Every warp covers ALL chunk columns (per-row lse state stays within one warp).
__global__ __launch_bounds__(256, 1) void logits_kernel(const float* __restrict__ queue) {
    __shared__ __align__(16) __nv_bfloat16 sB[2][128][72];   // 144B row stride
    const int tid = threadIdx.x, lane = tid & 31, w = tid >> 5;
    const int m0 = (blockIdx.x >> 1) * 128, n0 = (blockIdx.x & 1) * 512;
    unsigned base0 = (unsigned)__cvta_generic_to_shared(&sB[0][0][0]);
    unsigned base1 = (unsigned)__cvta_generic_to_shared(&sB[1][0][0]);

    // extract A fragments in two passes through sB[0] (k-cols 0:64 then 64:128)
    unsigned af[8][4];
#pragma unroll
    for (int s = 0; s < 2; s++) {
        if (s == 1) __syncthreads();
#pragma unroll
        for (int it = 0; it < 8; it++) {
            int lin = it * 256 + tid;
            int row = lin >> 4, c4 = (lin & 15) * 4;
            float4 v = *reinterpret_cast<const float4*>(g_q + (m0 + row) * EMB + s * 64 + c4);
            *reinterpret_cast<uint2*>(&sB[0][row][c4]) = f4bf(v);
        }
        __syncthreads();
#pragma unroll
        for (int k = 0; k < 4; k++) {
            int row = w * 16 + (lane & 15);
            int col = k * 16 + (lane >> 4) * 8;
            ldsm4(af[s * 4 + k][0], af[s * 4 + k][1], af[s * 4 + k][2], af[s * 4 + k][3],
                  base0 + (unsigned)(row * 72 + col) * 2u);
        }
    }

    // preload chunk 0 into sB[1]
    float4 rq[8];
#pragma unroll
    for (int it = 0; it < 8; it++) {
        int lin = it * 256 + tid;
        rq[it] = *reinterpret_cast<const float4*>(queue + (lin >> 4) * QN + n0 + (lin & 15) * 4);
    }
#pragma unroll
    for (int it = 0; it < 8; it++) {
        int lin = it * 256 + tid;
        *reinterpret_cast<uint2*>(&sB[1][lin >> 4][(lin & 15) * 4]) = f4bf(rq[it]);
    }
    __syncthreads();

    float m0r = -1e30f, m1r = -1e30f, l0r = 0.f, l1r = 0.f;
    for (int ch = 0; ch < 8; ch++) {
        const int rb = (ch & 1) ^ 1;
        if (ch < 7) {
#pragma unroll
            for (int it = 0; it < 8; it++) {
                int lin = it * 256 + tid;
                rq[it] = *reinterpret_cast<const float4*>(
                    queue + (lin >> 4) * QN + n0 + (ch + 1) * 64 + (lin & 15) * 4);
            }
        }
        unsigned bbase = rb ? base1 : base0;
        float acc[8][4];
#pragma unroll
        for (int nt = 0; nt < 8; nt++) { acc[nt][0] = acc[nt][1] = acc[nt][2] = acc[nt][3] = 0.f; }
#pragma unroll
        for (int ks = 0; ks < 8; ks++) {
            unsigned bfr[4][4];
#pragma unroll
            for (int p = 0; p < 4; p++) {
                int qd = lane >> 3;
                int row = ks * 16 + (qd & 1) * 8 + (lane & 7);
                int col = p * 16 + (qd >> 1) * 8;
                ldsm4t(bfr[p][0], bfr[p][1], bfr[p][2], bfr[p][3],
                       bbase + (unsigned)(row * 72 + col) * 2u);
            }
#pragma unroll
            for (int nt = 0; nt < 8; nt++)
                mma16816(acc[nt], af[ks], bfr[nt >> 1][(nt & 1) * 2], bfr[nt >> 1][(nt & 1) * 2 + 1]);
        }
        float c0 = -1e30f, c1 = -1e30f;
#pragma unroll
        for (int nt = 0; nt < 8; nt++) {
            c0 = fmaxf(c0, fmaxf(acc[nt][0], acc[nt][1]));
            c1 = fmaxf(c1, fmaxf(acc[nt][2], acc[nt][3]));
        }
        c0 = fmaxf(c0, __shfl_xor_sync(0xffffffffu, c0, 1));
        c0 = fmaxf(c0, __shfl_xor_sync(0xffffffffu, c0, 2));
        c1 = fmaxf(c1, __shfl_xor_sync(0xffffffffu, c1, 1));
        c1 = fmaxf(c1, __shfl_xor_sync(0xffffffffu, c1, 2));
        float n0m = fmaxf(m0r, c0), n1m = fmaxf(m1r, c1);
        float s0 = 0.f, s1 = 0.f;
#pragma unroll
        for (int nt = 0; nt < 8; nt++) {
            s0 += __expf(acc[nt][0] - n0m) + __expf(acc[nt][1] - n0m);
            s1 += __expf(acc[nt][2] - n1m) + __expf(acc[nt][3] - n1m);
        }
        s0 += __shfl_xor_sync(0xffffffffu, s0, 1);
        s0 += __shfl_xor_sync(0xffffffffu, s0, 2);
        s1 += __shfl_xor_sync(0xffffffffu, s1, 1);
        s1 += __shfl_xor_sync(0xffffffffu, s1, 2);
        l0r = l0r * __expf(m0r - n0m) + s0; m0r = n0m;
        l1r = l1r * __expf(m1r - n1m) + s1; m1r = n1m;
        if (ch < 7) {
#pragma unroll
            for (int it = 0; it < 8; it++) {
                int lin = it * 256 + tid;
                *reinterpret_cast<uint2*>(&sB[rb ^ 1][lin >> 4][(lin & 15) * 4]) = f4bf(rq[it]);
            }
        }
        __syncthreads();
    }
    if ((lane & 3) == 0) {
        int half = blockIdx.x & 1;
        int r = m0 + w * 16 + (lane >> 2);
        g_m[half * NW + r] = m0r;      g_l[half * NW + r] = l0r;
        g_m[half * NW + r + 8] = m1r;  g_l[half * NW + r + 8] = l1r;
    }
}

// ---------------- per-row CE + partial reduction ----------------
__global__ void row_ce_kernel() {
    const int tid = threadIdx.x, lane = tid & 31, wid = tid >> 5;
    int i = blockIdx.x * 256 + tid;
    float ma = g_m[i], la = g_l[i], mb = g_m[NW + i], lb = g_l[NW + i];
    float M = fmaxf(ma, mb);
    float L = la * __expf(ma - M) + lb * __expf(mb - M);
    const float4* qa = reinterpret_cast<const float4*>(g_q + i * EMB);
    const float4* ka = reinterpret_cast<const float4*>(g_k + g_idx[i] * EMB);
    float s = 0.f;
#pragma unroll
    for (int j = 0; j < EMB / 4; j++) {
        float4 a = qa[j], b = ka[j];
        s += a.x * b.x + a.y * b.y + a.z * b.z + a.w * b.w;
    }
    float lpos = s;
    float Mf = fmaxf(M, lpos);
    float Lf = L * __expf(M - Mf) + __expf(lpos - Mf);
    float ce = Mf + logf(Lf) - lpos;
    float v = g_valid[i] ? 1.f : 0.f;
    float aS = ce * v, cS = v;
#pragma unroll
    for (int o = 16; o; o >>= 1) {
        aS += __shfl_xor_sync(0xffffffffu, aS, o);
        cS += __shfl_xor_sync(0xffffffffu, cS, o);
    }
    __shared__ float rs[8], rc[8];
    if (lane == 0) { rs[wid] = aS; rc[wid] = cS; }
    __syncthreads();
    if (tid == 0) {
        float A = 0, C = 0;
#pragma unroll
        for (int ww = 0; ww < 8; ww++) { A += rs[ww]; C += rc[ww]; }
        g_psum[blockIdx.x] = A;
        g_pcnt[blockIdx.x] = C;
    }
}

__global__ void final_kernel(float* out) {
    int lane = threadIdx.x;
    float s = g_psum[lane], c = g_pcnt[lane];
#pragma unroll
    for (int o = 16; o; o >>= 1) {
        s += __shfl_xor_sync(0xffffffffu, s, o);
        c += __shfl_xor_sync(0xffffffffu, c, o);
    }
    if (lane == 0) out[0] = s / fmaxf(c, 1.f);
}

// ---------------- launch ----------------
extern "C" void kernel_launch(void* const* d_in, const int* in_sizes, int n_in,
                              void* d_out, int out_size) {
    const float* fs    = (const float*)d_in[0];   // feats_strong [8192,1024]
    const float* fw    = (const float*)d_in[1];   // feats_weak   [8192,1024]
    const int*   slab  = (const int*)d_in[2];     // strong_labels (int32)
    const int*   wlab  = (const int*)d_in[3];     // weak_labels   (int32)
    const float* Wq    = (const float*)d_in[4];
    const float* bq    = (const float*)d_in[5];
    const float* Wk    = (const float*)d_in[6];
    const float* bk    = (const float*)d_in[7];
    const float* queue = (const float*)d_in[8];   // [1024,128] flat
    float* out = (float*)d_out;

    label_scan_kernel<<<2 * NC, 256>>>(slab, wlab);
    idx_kernel<<<NW / 256, 256>>>(wlab);
    encoder_gemm_kernel<<<256, 256>>>(fw, fs, Wq, bq, Wk, bk);
    logits_kernel<<<128, 256>>>(queue);
    row_ce_kernel<<<NW / 256, 256>>>();
    final_kernel<<<1, 32>>>(out);
}